// round 10
// baseline (speedup 1.0000x reference)
#include <cuda_runtime.h>
#include <cuda_bf16.h>
#include <cuda_fp16.h>
#include <cstdint>

#define N_SRC   50000
#define N_DST   50000
#define N_EDGES 800000
#define D       128

// ---------------- device-global scratch (allocation-free) ----------------
__device__ __align__(16) __half g_nsrc_h[N_SRC * D];  // fp16 relu(Q h_src + b)
__device__ int   g_cnt[N_DST];
__device__ int   g_startv[N_DST];
__device__ int   g_cursor[N_DST];
__device__ int   g_total;
__device__ __align__(8) uint2 g_edge[N_EDGES];        // packed (src, weight)
// Pre-packed bf16 hi/lo operands for gemm1 (u32 = bf16x2)
__device__ __align__(16) uint32_t g_Ahi[N_DST * 64], g_Alo[N_DST * 64]; // aggregate
__device__ __align__(16) uint32_t g_Dhi[N_DST * 64], g_Dlo[N_DST * 64]; // h_dst
// Pre-packed weights: [j][KDIM/2] u32
__device__ __align__(16) uint32_t g_Qhi[128 * 64],  g_Qlo[128 * 64];
__device__ __align__(16) uint32_t g_Whi[128 * 128], g_Wlo[128 * 128];

// ---------------------------------------------------------------------------
// bf16x3 split helpers
// ---------------------------------------------------------------------------
__device__ __forceinline__ void pack2(float x, float y,
                                      uint32_t& hi, uint32_t& lo) {
    __nv_bfloat162 h = __floats2bfloat162_rn(x, y);
    uint32_t hu = reinterpret_cast<uint32_t&>(h);
    float fx = __uint_as_float(hu << 16);
    float fy = __uint_as_float(hu & 0xFFFF0000u);
    __nv_bfloat162 l = __floats2bfloat162_rn(x - fx, y - fy);
    hi = hu;
    lo = reinterpret_cast<uint32_t&>(l);
}

__device__ __forceinline__ void mma_bf16(float* d, const uint32_t* a,
                                         const uint32_t* b) {
    asm volatile(
        "mma.sync.aligned.m16n8k16.row.col.f32.bf16.bf16.f32 "
        "{%0,%1,%2,%3}, {%4,%5,%6,%7}, {%8,%9}, {%0,%1,%2,%3};"
        : "+f"(d[0]), "+f"(d[1]), "+f"(d[2]), "+f"(d[3])
        : "r"(a[0]), "r"(a[1]), "r"(a[2]), "r"(a[3]),
          "r"(b[0]), "r"(b[1]));
}

// ---------------------------------------------------------------------------
// Fused prep: zero g_cnt + g_total, pre-pack Q_w / W_w.
// ---------------------------------------------------------------------------
__global__ void prep_kernel(const float* __restrict__ Qw,
                            const float* __restrict__ Ww) {
    const int nq = 128 * 64, nw = 128 * 128;
    int i = blockIdx.x * blockDim.x + threadIdx.x;
    if (i < N_DST) g_cnt[i] = 0;
    if (i == 0)    g_total = 0;
    if (i < nq) {
        float2 v = *(const float2*)(Qw + i * 2);
        pack2(v.x, v.y, g_Qhi[i], g_Qlo[i]);
    } else if (i < nq + nw) {
        int j = i - nq;
        float2 v = *(const float2*)(Ww + j * 2);
        pack2(v.x, v.y, g_Whi[j], g_Wlo[j]);
    }
}

// Pre-pack h_dst [N_DST x 128] fp32 -> bf16 hi/lo (runs on its own stream,
// overlapped with gemm0 + CSR build; only needed by gemm1).
__global__ void prepack_hdst_kernel(const float* __restrict__ hdst) {
    int i = blockIdx.x * blockDim.x + threadIdx.x;   // u32 index
    if (i >= N_DST * 64) return;
    float2 v = *(const float2*)(hdst + (size_t)i * 2);
    pack2(v.x, v.y, g_Dhi[i], g_Dlo[i]);
}

// ---------------------------------------------------------------------------
// CSR build: histogram -> atomic segment alloc -> scatter (packed 8B stores)
// ---------------------------------------------------------------------------
__global__ void hist_kernel(const int* __restrict__ edst) {
    int e = blockIdx.x * blockDim.x + threadIdx.x;
    if (e < N_EDGES) atomicAdd(&g_cnt[edst[e]], 1);
}

__global__ void alloc_kernel() {
    const int i    = blockIdx.x * blockDim.x + threadIdx.x;
    const int lane = threadIdx.x & 31;
    int c = (i < N_DST) ? g_cnt[i] : 0;
    int pfx = c;
#pragma unroll
    for (int o = 1; o < 32; o <<= 1) {
        int v = __shfl_up_sync(0xffffffffu, pfx, o);
        if (lane >= o) pfx += v;
    }
    int wtot = __shfl_sync(0xffffffffu, pfx, 31);
    int wbase = 0;
    if (lane == 31) wbase = atomicAdd(&g_total, wtot);
    wbase = __shfl_sync(0xffffffffu, wbase, 31);
    if (i < N_DST) {
        int base = wbase + pfx - c;
        g_startv[i] = base;
        g_cursor[i] = base;
    }
}

__global__ void scatter_kernel(const int* __restrict__ esrc,
                               const int* __restrict__ edst,
                               const float* __restrict__ weights) {
    int e = blockIdx.x * blockDim.x + threadIdx.x;
    if (e >= N_EDGES) return;
    int d   = edst[e];
    int pos = atomicAdd(&g_cursor[d], 1);
    g_edge[pos] = make_uint2((uint32_t)esrc[e], __float_as_uint(weights[e]));
}

// ---------------------------------------------------------------------------
// Aggregation: one warp per dst, fp16 gather (x4 unroll), fp32 accumulate,
// normalized output written pre-packed as bf16 hi/lo for gemm1.
// ---------------------------------------------------------------------------
__global__ void aggregate_csr_kernel() {
    const int warp = (blockIdx.x * blockDim.x + threadIdx.x) >> 5;
    const int lane = threadIdx.x & 31;
    if (warp >= N_DST) return;

    const int beg = g_startv[warp];
    const int n   = g_cnt[warp];

    float4 acc = make_float4(0.f, 0.f, 0.f, 0.f);
    float  wsum = 0.f;

#define ACC_H2(raw, ww) {                                                   \
        float2 p0 = __half22float2(*reinterpret_cast<__half2*>(&(raw).x)); \
        float2 p1 = __half22float2(*reinterpret_cast<__half2*>(&(raw).y)); \
        acc.x = fmaf(p0.x, (ww), acc.x);                                   \
        acc.y = fmaf(p0.y, (ww), acc.y);                                   \
        acc.z = fmaf(p1.x, (ww), acc.z);                                   \
        acc.w = fmaf(p1.y, (ww), acc.w); }

    int i = 0;
    for (; i + 4 <= n; i += 4) {
        uint2 e0 = g_edge[beg + i],     e1 = g_edge[beg + i + 1];
        uint2 e2 = g_edge[beg + i + 2], e3 = g_edge[beg + i + 3];
        uint2 r0 = *(const uint2*)(g_nsrc_h + (size_t)e0.x * D + lane * 4);
        uint2 r1 = *(const uint2*)(g_nsrc_h + (size_t)e1.x * D + lane * 4);
        uint2 r2 = *(const uint2*)(g_nsrc_h + (size_t)e2.x * D + lane * 4);
        uint2 r3 = *(const uint2*)(g_nsrc_h + (size_t)e3.x * D + lane * 4);
        float w0 = __uint_as_float(e0.y), w1 = __uint_as_float(e1.y);
        float w2 = __uint_as_float(e2.y), w3 = __uint_as_float(e3.y);
        ACC_H2(r0, w0); ACC_H2(r1, w1); ACC_H2(r2, w2); ACC_H2(r3, w3);
        wsum += (w0 + w1) + (w2 + w3);
    }
    for (; i < n; ++i) {
        uint2 e = g_edge[beg + i];
        float w = __uint_as_float(e.y);
        uint2 r = *(const uint2*)(g_nsrc_h + (size_t)e.x * D + lane * 4);
        ACC_H2(r, w);
        wsum += w;
    }
#undef ACC_H2

    const float inv = 1.0f / fmaxf(wsum, 1.0f);
    uint32_t h0, l0, h1, l1;
    pack2(acc.x * inv, acc.y * inv, h0, l0);
    pack2(acc.z * inv, acc.w * inv, h1, l1);
    const size_t o = (size_t)warp * 64 + lane * 2;
    *(uint2*)(g_Ahi + o) = make_uint2(h0, h1);
    *(uint2*)(g_Alo + o) = make_uint2(l0, l1);
}

// ---------------------------------------------------------------------------
// Tensor-core GEMM (bf16x3): OUT[i][j] = relu(sum_k A[i][k]*W[j][k] + bias[j])
//   MODE 0: A = h_src fp32 (packed in-kernel), KDIM=128, OUT = g_nsrc_h (fp16)
//   MODE 1: A = [g_Ahi/lo | g_Dhi/lo] pre-packed, KDIM=256, OUT = d_out (fp32)
// ---------------------------------------------------------------------------
template <int KDIM, int MODE>
__global__ void __launch_bounds__(256, 2)
gemm_bf16x3(const float* __restrict__ A0,
            const float* __restrict__ bias,
            float* __restrict__ out,
            int nrows)
{
    constexpr int P  = 20;
    constexpr int K2 = KDIM / 2;
    const uint32_t* __restrict__ Bhi = (MODE == 0) ? g_Qhi : g_Whi;
    const uint32_t* __restrict__ Blo = (MODE == 0) ? g_Qlo : g_Wlo;

    __shared__ uint32_t As_hi[128 * P];
    __shared__ uint32_t As_lo[128 * P];
    __shared__ uint32_t Bs_hi[128 * P];
    __shared__ uint32_t Bs_lo[128 * P];

    const int tid    = threadIdx.x;
    const int i0     = blockIdx.x * 128;
    const int lane   = tid & 31;
    const int wid    = tid >> 5;
    const int warp_m = wid & 3;
    const int warp_n = wid >> 2;
    const int qr     = lane >> 2;
    const int qc     = lane & 3;

    float acc[2][8][4];
#pragma unroll
    for (int mt = 0; mt < 2; ++mt)
#pragma unroll
        for (int nt = 0; nt < 8; ++nt)
#pragma unroll
            for (int r = 0; r < 4; ++r) acc[mt][nt][r] = 0.f;

    const int  lrow = tid >> 1;
    const int  lkq  = (tid & 1) * 16;
    const int  gi   = i0 + lrow;
    const bool ok   = (gi < nrows);

    for (int kc = 0; kc < KDIM; kc += 32) {
        __syncthreads();

#pragma unroll
        for (int q = 0; q < 4; ++q) {
            const int gk = kc + lkq + q * 4;
            const int k2 = (lkq + q * 4) >> 1;
            uint2 ah = make_uint2(0u, 0u), al = make_uint2(0u, 0u);
            if (MODE == 0) {
                if (ok) {
                    float4 av = *(const float4*)(A0 + (size_t)gi * 128 + gk);
                    uint32_t h0, l0, h1, l1;
                    pack2(av.x, av.y, h0, l0);
                    pack2(av.z, av.w, h1, l1);
                    ah = make_uint2(h0, h1);
                    al = make_uint2(l0, l1);
                }
            } else {
                if (ok) {
                    if (gk < 128) {
                        const size_t idx = (size_t)gi * 64 + (gk >> 1);
                        ah = *(const uint2*)(g_Ahi + idx);
                        al = *(const uint2*)(g_Alo + idx);
                    } else {
                        const size_t idx = (size_t)gi * 64 + ((gk - 128) >> 1);
                        ah = *(const uint2*)(g_Dhi + idx);
                        al = *(const uint2*)(g_Dlo + idx);
                    }
                }
            }
            *(uint2*)(As_hi + lrow * P + k2) = ah;
            *(uint2*)(As_lo + lrow * P + k2) = al;
            const int bidx = lrow * K2 + (gk >> 1);
            *(uint2*)(Bs_hi + lrow * P + k2) = *(const uint2*)(Bhi + bidx);
            *(uint2*)(Bs_lo + lrow * P + k2) = *(const uint2*)(Blo + bidx);
        }
        __syncthreads();

#pragma unroll
        for (int s = 0; s < 2; ++s) {
            const int ks = s * 8;
            uint32_t ahi[2][4], alo[2][4];
#pragma unroll
            for (int mt = 0; mt < 2; ++mt) {
                const int base = (warp_m * 32 + mt * 16 + qr) * P + ks + qc;
                ahi[mt][0] = As_hi[base];
                ahi[mt][1] = As_hi[base + 8 * P];
                ahi[mt][2] = As_hi[base + 4];
                ahi[mt][3] = As_hi[base + 8 * P + 4];
                alo[mt][0] = As_lo[base];
                alo[mt][1] = As_lo[base + 8 * P];
                alo[mt][2] = As_lo[base + 4];
                alo[mt][3] = As_lo[base + 8 * P + 4];
            }
#pragma unroll
            for (int nt = 0; nt < 8; ++nt) {
                const int bb = (warp_n * 64 + nt * 8 + qr) * P + ks + qc;
                uint32_t bh[2] = { Bs_hi[bb], Bs_hi[bb + 4] };
                uint32_t bl[2] = { Bs_lo[bb], Bs_lo[bb + 4] };
#pragma unroll
                for (int mt = 0; mt < 2; ++mt) {
                    mma_bf16(acc[mt][nt], ahi[mt], bh);
                    mma_bf16(acc[mt][nt], alo[mt], bh);
                    mma_bf16(acc[mt][nt], ahi[mt], bl);
                }
            }
        }
    }

#pragma unroll
    for (int mt = 0; mt < 2; ++mt) {
#pragma unroll
        for (int half = 0; half < 2; ++half) {
            const int row = i0 + warp_m * 32 + mt * 16 + qr + half * 8;
            if (row < nrows) {
#pragma unroll
                for (int nt = 0; nt < 8; ++nt) {
                    const int col = warp_n * 64 + nt * 8 + qc * 2;
                    float vx = fmaxf(acc[mt][nt][half * 2 + 0] + bias[col],     0.f);
                    float vy = fmaxf(acc[mt][nt][half * 2 + 1] + bias[col + 1], 0.f);
                    if (MODE == 0) {
                        *(__half2*)(g_nsrc_h + (size_t)row * 128 + col) =
                            __floats2half2_rn(vx, vy);
                    } else {
                        *(float2*)(out + (size_t)row * 128 + col) =
                            make_float2(vx, vy);
                    }
                }
            }
        }
    }
}

// ---------------------------------------------------------------------------
// Launch graph:
//   main: prep -> gemm0 --------------------------> agg -> gemm1
//   s2:        \-> hist -> alloc -> scatter --/joinA      /
//   s3:        \-> prepack_hdst ------------------joinB--/
// ---------------------------------------------------------------------------
extern "C" void kernel_launch(void* const* d_in, const int* in_sizes, int n_in,
                              void* d_out, int out_size)
{
    const float* h_src   = (const float*)d_in[0];
    const float* h_dst   = (const float*)d_in[1];
    const float* weights = (const float*)d_in[2];
    const int*   esrc    = (const int*)d_in[3];
    const int*   edst    = (const int*)d_in[4];
    const float* Q_w     = (const float*)d_in[5];
    const float* Q_b     = (const float*)d_in[6];
    const float* W_w     = (const float*)d_in[7];
    const float* W_b     = (const float*)d_in[8];
    float*       out     = (float*)d_out;

    static cudaStream_t s2 = nullptr, s3 = nullptr;
    static cudaEvent_t  evFork = nullptr, evJoinA = nullptr, evJoinB = nullptr;
    if (!s2) {
        cudaStreamCreateWithFlags(&s2, cudaStreamNonBlocking);
        cudaStreamCreateWithFlags(&s3, cudaStreamNonBlocking);
        cudaEventCreateWithFlags(&evFork,  cudaEventDisableTiming);
        cudaEventCreateWithFlags(&evJoinA, cudaEventDisableTiming);
        cudaEventCreateWithFlags(&evJoinB, cudaEventDisableTiming);
    }

    prep_kernel<<<(N_DST + 255) / 256, 256>>>(Q_w, W_w);

    cudaEventRecord(evFork, 0);
    cudaStreamWaitEvent(s2, evFork, 0);
    cudaStreamWaitEvent(s3, evFork, 0);

    // s2: CSR build
    hist_kernel<<<(N_EDGES + 255) / 256, 256, 0, s2>>>(edst);
    alloc_kernel<<<(N_DST + 255) / 256, 256, 0, s2>>>();
    scatter_kernel<<<(N_EDGES + 255) / 256, 256, 0, s2>>>(esrc, edst, weights);
    cudaEventRecord(evJoinA, s2);

    // s3: h_dst prepack (only needed by gemm1)
    prepack_hdst_kernel<<<(N_DST * 64 + 255) / 256, 256, 0, s3>>>(h_dst);
    cudaEventRecord(evJoinB, s3);

    // main: GEMM0 (overlaps s2 + s3)
    gemm_bf16x3<128, 0><<<(N_SRC + 127) / 128, 256>>>(h_src, Q_b, nullptr, N_SRC);

    cudaStreamWaitEvent(0, evJoinA, 0);
    aggregate_csr_kernel<<<(N_DST * 32 + 255) / 256, 256>>>();

    cudaStreamWaitEvent(0, evJoinB, 0);
    gemm_bf16x3<256, 1><<<(N_DST + 127) / 128, 256>>>(nullptr, W_b, out, N_DST);
}